// round 2
// baseline (speedup 1.0000x reference)
#include <cuda_runtime.h>
#include <cuda_bf16.h>
#include <cstdint>

// ============================================================================
// HQQ grouped int4 GEMM — sm_103 BASE target (no tcgen05/TMA: ptxas rejects
// arch-suffix features here). Legacy mma.sync.m16n8k16 bf16 path with fp32
// accumulate and a bf16 hi/lo split of BOTH operands for precision:
//   x@W ≈ xh@Wh + xl@Wh + xh@Wl   (xl@Wl ~ 4e-6, dropped)
// ============================================================================

namespace {

constexpr int kE   = 8;
constexpr int kT   = 2048;
constexpr int kIN  = 2048;
constexpr int kOUT = 2048;
constexpr int kG   = 32;                  // quant groups (IN/64)

constexpr int kBM  = 128;
constexpr int kBN  = 128;
constexpr int kBK  = 64;                  // == group size
constexpr int kNCh = kIN / kBK;           // 32 chunks
constexpr int kThreads = 512;             // 16 warps, 4x4 warp grid

constexpr int kTileB  = kBM * kBK * 2;    // 16 KB per bf16 tile
constexpr int kStageB = 4 * kTileB;       // A_hi A_lo B_hi B_lo = 64 KB
constexpr int kSmemB  = 2 * kStageB;      // 128 KB double buffered

// ---------------------------------------------------------------------------

__device__ __forceinline__ uint32_t smem_u32(const void* p) {
  uint32_t a;
  asm("{ .reg .u64 t; cvta.to.shared.u64 t, %1; cvt.u32.u64 %0, t; }" : "=r"(a) : "l"(p));
  return a;
}

// pack: lo -> low 16 bits (lower address), hi -> high
__device__ __forceinline__ uint32_t pack_bf16x2(float lo, float hi) {
  uint32_t r;
  asm("cvt.rn.bf16x2.f32 %0, %1, %2;" : "=r"(r) : "f"(hi), "f"(lo));
  return r;
}

__device__ __forceinline__ float2 unpack_bf16x2(uint32_t u) {
  __nv_bfloat162 h;
  *reinterpret_cast<uint32_t*>(&h) = u;
  return make_float2(__bfloat162float(h.x), __bfloat162float(h.y));
}

__device__ __forceinline__ uint32_t sw128(uint32_t off) {
  return off ^ ((off >> 3) & 0x70);
}

__device__ __forceinline__ void ldsm_x4(uint32_t* r, uint32_t addr) {
  asm volatile("ldmatrix.sync.aligned.m8n8.x4.shared.b16 {%0,%1,%2,%3}, [%4];"
               : "=r"(r[0]), "=r"(r[1]), "=r"(r[2]), "=r"(r[3]) : "r"(addr));
}

__device__ __forceinline__ void ldsm_x2(uint32_t* r, uint32_t addr) {
  asm volatile("ldmatrix.sync.aligned.m8n8.x2.shared.b16 {%0,%1}, [%2];"
               : "=r"(r[0]), "=r"(r[1]) : "r"(addr));
}

__device__ __forceinline__ void mma_bf16(float* c, const uint32_t* a, const uint32_t* b) {
  asm volatile(
      "mma.sync.aligned.m16n8k16.row.col.f32.bf16.bf16.f32 "
      "{%0,%1,%2,%3}, {%4,%5,%6,%7}, {%8,%9}, {%0,%1,%2,%3};"
      : "+f"(c[0]), "+f"(c[1]), "+f"(c[2]), "+f"(c[3])
      : "r"(a[0]), "r"(a[1]), "r"(a[2]), "r"(a[3]), "r"(b[0]), "r"(b[1]));
}

// ---------------------------------------------------------------------------

__global__ void __launch_bounds__(kThreads)
hqq_mma_kernel(const float* __restrict__ x,
               const int* __restrict__ qw,
               const float* __restrict__ snz,
               const int* __restrict__ tpe,
               float* __restrict__ out) {
  extern __shared__ __align__(1024) char smem[];
  const int tid = threadIdx.x;
  const int wid = tid >> 5;
  const int l   = tid & 31;

  const int e  = blockIdx.z;
  const int nt = blockIdx.x;
  const int mt = blockIdx.y;

  int off = 0, cnt = 0;
#pragma unroll
  for (int i = 0; i < kE; i++) {
    int c = __ldg(&tpe[i]);
    if (i < e) off += c;
    if (i == e) cnt = c;
  }
  if (mt * kBM >= cnt) return;

  const int row0  = off + mt * kBM;
  const int nrows = min(kBM, cnt - mt * kBM);
  const int n0    = nt * kBN;

  const uint32_t sbase = smem_u32(smem);

  // ---- fill-index mapping (see theory: bank-conflict-free under SW128) ----
  // A: pair-col pc = lane, rows m = wid + 16p
  const int a_pc = l;
  // B: n = (wid&7)*16 + (l>>2) + 8*(p&1);  kp = (wid>>3)*16 + (l&3) + 4*(p>>1)
  const int b_nb = (wid & 7) * 16 + (l >> 2);
  const int b_kb = (wid >> 3) * 16 + (l & 3);

  // ---- mma fragment addressing (per-thread constants) ----
  const int wm = wid >> 2;          // 0..3 -> m base 32*wm
  const int wn = wid & 3;           // 0..3 -> n base 32*wn
  const int rowA0 = wm * 32 + (l & 15);        // + mi*16
  const int segA  = (l >> 4);                  // 0/1 -> +16B
  const int rowB0 = wn * 32 + (l & 7);         // + ni*8
  const int segB  = (l >> 3) & 1;

  // ---- staging registers for the software pipeline ----
  float2 xv[8];
  int    qv0[8], qv1[8];
  float2 szv[2];

  float acc[32];
#pragma unroll
  for (int i = 0; i < 32; i++) acc[i] = 0.f;

  auto load_chunk = [&](int ch) {
    const int k0 = ch * kBK;
    const float* xp = x + (size_t)row0 * kIN + k0 + 2 * a_pc;
#pragma unroll
    for (int p = 0; p < 8; p++) {
      const int m = wid + p * 16;
      xv[p] = (m < nrows) ? *(const float2*)(xp + (size_t)m * kIN)
                          : make_float2(0.f, 0.f);
    }
    const int* qb = qw + ((size_t)e * kIN + k0) * kOUT + n0;
#pragma unroll
    for (int p = 0; p < 8; p++) {
      const int n  = b_nb + (p & 1) * 8;
      const int kk = 2 * (b_kb + (p >> 1) * 4);
      qv0[p] = __ldg(qb + (size_t)kk * kOUT + n);
      qv1[p] = __ldg(qb + (size_t)(kk + 1) * kOUT + n);
    }
    const float* sp = snz + (((size_t)e * kG + ch) * kOUT + n0 + b_nb) * 2;
    szv[0] = *(const float2*)(sp);
    szv[1] = *(const float2*)(sp + 16);   // n + 8 -> +16 floats
  };

  auto store_chunk = [&](int buf) {
    char* A_hi = smem + buf * kStageB;
    char* A_lo = A_hi + kTileB;
    char* B_hi = A_hi + 2 * kTileB;
    char* B_lo = A_hi + 3 * kTileB;
#pragma unroll
    for (int p = 0; p < 8; p++) {
      const int m = wid + p * 16;
      const float2 v = xv[p];
      const uint32_t h  = pack_bf16x2(v.x, v.y);
      const float2  hf  = unpack_bf16x2(h);
      const uint32_t lo = pack_bf16x2(v.x - hf.x, v.y - hf.y);
      const uint32_t o  = sw128((uint32_t)(m * 128 + a_pc * 4));
      *(uint32_t*)(A_hi + o) = h;
      *(uint32_t*)(A_lo + o) = lo;
    }
#pragma unroll
    for (int p = 0; p < 8; p++) {
      const int n  = b_nb + (p & 1) * 8;
      const int kp = b_kb + (p >> 1) * 4;
      const float s  = szv[p & 1].x;
      const float zp = szv[p & 1].y - 8.f * s;
      const float w0 = (float)qv0[p] * s + zp;
      const float w1 = (float)qv1[p] * s + zp;
      const uint32_t h  = pack_bf16x2(w0, w1);
      const float2  hf  = unpack_bf16x2(h);
      const uint32_t lo = pack_bf16x2(w0 - hf.x, w1 - hf.y);
      const uint32_t o  = sw128((uint32_t)(n * 128 + kp * 4));
      *(uint32_t*)(B_hi + o) = h;
      *(uint32_t*)(B_lo + o) = lo;
    }
  };

  auto mma_chunk = [&](int buf) {
    const uint32_t base = sbase + buf * kStageB;
#pragma unroll
    for (int ks = 0; ks < 4; ks++) {
      uint32_t Ah[2][4], Al[2][4], Bh[4][2], Bl[4][2];
#pragma unroll
      for (int mi = 0; mi < 2; mi++) {
        const int row = rowA0 + mi * 16;
        const uint32_t o = (uint32_t)(row * 128) +
                           (((uint32_t)(ks * 32 + segA * 16)) ^ ((row & 7) << 4));
        ldsm_x4(Ah[mi], base + o);
        ldsm_x4(Al[mi], base + kTileB + o);
      }
#pragma unroll
      for (int ni = 0; ni < 4; ni++) {
        const int row = rowB0 + ni * 8;
        const uint32_t o = (uint32_t)(row * 128) +
                           (((uint32_t)(ks * 32 + segB * 16)) ^ ((row & 7) << 4));
        ldsm_x2(Bh[ni], base + 2 * kTileB + o);
        ldsm_x2(Bl[ni], base + 3 * kTileB + o);
      }
#pragma unroll
      for (int mi = 0; mi < 2; mi++)
#pragma unroll
        for (int ni = 0; ni < 4; ni++) {
          float* c = &acc[(mi * 4 + ni) * 4];
          mma_bf16(c, Ah[mi], Bh[ni]);
          mma_bf16(c, Al[mi], Bh[ni]);
          mma_bf16(c, Ah[mi], Bl[ni]);
        }
    }
  };

  // ---- software pipeline: LDG(ch+1) overlaps MMA(ch) ----
  load_chunk(0);
  for (int ch = 0; ch < kNCh; ch++) {
    const int buf = ch & 1;
    store_chunk(buf);
    __syncthreads();
    if (ch + 1 < kNCh) load_chunk(ch + 1);
    mma_chunk(buf);
    __syncthreads();   // buf reusable two iterations later
  }

  // ---- epilogue ----
#pragma unroll
  for (int mi = 0; mi < 2; mi++) {
#pragma unroll
    for (int ni = 0; ni < 4; ni++) {
      const float* c = &acc[(mi * 4 + ni) * 4];
      const int r0 = wm * 32 + mi * 16 + (l >> 2);
      const int col = n0 + wn * 32 + ni * 8 + (l & 3) * 2;
      if (r0 < nrows)
        *(float2*)(out + (size_t)(row0 + r0) * kOUT + col) = make_float2(c[0], c[1]);
      if (r0 + 8 < nrows)
        *(float2*)(out + (size_t)(row0 + r0 + 8) * kOUT + col) = make_float2(c[2], c[3]);
    }
  }
}

}  // namespace

// ---------------------------------------------------------------------------

extern "C" void kernel_launch(void* const* d_in, const int* in_sizes, int n_in,
                              void* d_out, int out_size) {
  (void)in_sizes; (void)n_in; (void)out_size;
  const float* x   = (const float*)d_in[0];
  const int*   qw  = (const int*)d_in[1];
  const float* snz = (const float*)d_in[2];
  const int*   tpe = (const int*)d_in[3];
  float* out = (float*)d_out;

  (void)cudaFuncSetAttribute(hqq_mma_kernel,
                             cudaFuncAttributeMaxDynamicSharedMemorySize, kSmemB);

  dim3 grid(kOUT / kBN, kT / kBM, kE);   // (16, 16, 8); empty m-tiles early-exit
  hqq_mma_kernel<<<grid, kThreads, kSmemB>>>(x, qw, snz, tpe, out);
}

// round 4
// speedup vs baseline: 1.1124x; 1.1124x over previous
#include <cuda_runtime.h>
#include <cuda_bf16.h>
#include <cstdint>

// ============================================================================
// HQQ grouped int4 GEMM, sm_103 base target, mma.sync bf16 path.
//
// W = q*s + zp  (zp = z - 8s).  Per quant group g (== K-chunk of 64):
//     P_g      = (xh + xl) @ q_g          (q exact in bf16 -> exact products)
//     master  += P_g * s[g, n]            (fp32 FFMA in registers)
//     out     += R @ Z^T                  (rank-32 zero-point correction;
//                                          R, Z each split bf16 hi+lo, 3 terms)
// ============================================================================

namespace {

constexpr int kE   = 8;
constexpr int kIN  = 2048;
constexpr int kOUT = 2048;
constexpr int kG   = 32;

constexpr int kBM  = 128;
constexpr int kBN  = 128;
constexpr int kBK  = 64;                  // == group size
constexpr int kNCh = kIN / kBK;           // 32
constexpr int kThreads = 512;             // 16 warps, 4x4 warp grid

constexpr int kTileB  = kBM * kBK * 2;    // 16 KB bf16 tile
// stage: A_hi | A_lo | B_q | s[128] floats (512B); pad stride to 1KB multiple
constexpr int kStageB = 3 * kTileB + 1024;          // 50176
// correction region: R_hi | R_lo | Z_hi | Z_lo, each 128x32 bf16 = 8 KB
constexpr int kRZoff  = 2 * kStageB;
constexpr int kSmemB  = kRZoff + 4 * 8192;          // 133120

// ---------------------------------------------------------------------------

__device__ __forceinline__ uint32_t smem_u32(const void* p) {
  uint32_t a;
  asm("{ .reg .u64 t; cvta.to.shared.u64 t, %1; cvt.u32.u64 %0, t; }" : "=r"(a) : "l"(p));
  return a;
}

__device__ __forceinline__ uint32_t pack_bf16x2(float lo, float hi) {
  uint32_t r;
  asm("cvt.rn.bf16x2.f32 %0, %1, %2;" : "=r"(r) : "f"(hi), "f"(lo));
  return r;
}

__device__ __forceinline__ float2 unpack_bf16x2(uint32_t u) {
  __nv_bfloat162 h;
  *reinterpret_cast<uint32_t*>(&h) = u;
  return make_float2(__bfloat162float(h.x), __bfloat162float(h.y));
}

__device__ __forceinline__ uint32_t sw128(uint32_t off) {
  return off ^ ((off >> 3) & 0x70);
}

__device__ __forceinline__ void ldsm_x4(uint32_t* r, uint32_t addr) {
  asm volatile("ldmatrix.sync.aligned.m8n8.x4.shared.b16 {%0,%1,%2,%3}, [%4];"
               : "=r"(r[0]), "=r"(r[1]), "=r"(r[2]), "=r"(r[3]) : "r"(addr));
}

__device__ __forceinline__ void ldsm_x2(uint32_t* r, uint32_t addr) {
  asm volatile("ldmatrix.sync.aligned.m8n8.x2.shared.b16 {%0,%1}, [%2];"
               : "=r"(r[0]), "=r"(r[1]) : "r"(addr));
}

__device__ __forceinline__ void mma_bf16(float* c, const uint32_t* a, const uint32_t* b) {
  asm volatile(
      "mma.sync.aligned.m16n8k16.row.col.f32.bf16.bf16.f32 "
      "{%0,%1,%2,%3}, {%4,%5,%6,%7}, {%8,%9}, {%0,%1,%2,%3};"
      : "+f"(c[0]), "+f"(c[1]), "+f"(c[2]), "+f"(c[3])
      : "r"(a[0]), "r"(a[1]), "r"(a[2]), "r"(a[3]), "r"(b[0]), "r"(b[1]));
}

// ---------------------------------------------------------------------------

__global__ void __launch_bounds__(kThreads)
hqq_mma_kernel(const float* __restrict__ x,
               const int* __restrict__ qw,
               const float* __restrict__ snz,
               const int* __restrict__ tpe,
               float* __restrict__ out) {
  extern __shared__ __align__(1024) char smem[];
  const int tid = threadIdx.x;
  const int wid = tid >> 5;
  const int l   = tid & 31;

  const int e  = blockIdx.z;
  const int nt = blockIdx.x;
  const int mt = blockIdx.y;

  int off = 0, cnt = 0;
#pragma unroll
  for (int i = 0; i < kE; i++) {
    int c = __ldg(&tpe[i]);
    if (i < e) off += c;
    if (i == e) cnt = c;
  }
  if (mt * kBM >= cnt) return;

  const int row0  = off + mt * kBM;
  const int nrows = min(kBM, cnt - mt * kBM);
  const int n0    = nt * kBN;

  const uint32_t sbase = smem_u32(smem);

  // ---- fill mappings ----
  // A: float4 col c4 = l&15 (k = 4*c4 .. 4*c4+3), rows m = (tid>>4) + 32p
  const int a_c4 = l & 15;
  const int a_mr = tid >> 4;
  // B: row pair (b_n0, b_n0+1); k-pair base; per pass p: kp = b_kpb + 4p
  const int b_n0  = 2 * ((wid & 7) * 8 + (l >> 2));
  const int b_kpb = (wid >> 3) * 16 + (l & 3);

  // ---- mma fragment addressing ----
  const int wm = wid >> 2;
  const int wn = wid & 3;
  const int rowA0 = wm * 32 + (l & 15);
  const int segA  = l >> 4;
  const int rowB0 = wn * 32 + (l & 7);
  const int segB  = (l >> 3) & 1;

  // ---- staging ----
  float4 xv[4];
  int2   qva[4], qvb[4];
  float2 szv = make_float2(0.f, 0.f);

  float mast[32];
#pragma unroll
  for (int i = 0; i < 32; i++) mast[i] = 0.f;

  auto load_chunk = [&](int ch) {
    const int k0 = ch * kBK;
    const float* xp = x + ((size_t)(row0 + a_mr)) * kIN + k0 + a_c4 * 4;
#pragma unroll
    for (int p = 0; p < 4; p++) {
      const int m = a_mr + p * 32;
      xv[p] = (m < nrows) ? *(const float4*)(xp + (size_t)p * 32 * kIN)
                          : make_float4(0.f, 0.f, 0.f, 0.f);
    }
    const int* qb = qw + ((size_t)e * kIN + k0) * kOUT + n0 + b_n0;
#pragma unroll
    for (int p = 0; p < 4; p++) {
      const int kk = 2 * (b_kpb + 4 * p);
      qva[p] = *(const int2*)(qb + (size_t)kk * kOUT);
      qvb[p] = *(const int2*)(qb + (size_t)(kk + 1) * kOUT);
    }
    if (tid < 128)
      szv = *(const float2*)(snz + (((size_t)e * kG + ch) * kOUT + n0 + tid) * 2);
  };

  auto store_chunk = [&](int buf, int ch) {
    char* st = smem + buf * kStageB;
    // A tiles: fp32 -> bf16 hi/lo, SW128; one float4 -> 8 bytes at col c4*8
#pragma unroll
    for (int p = 0; p < 4; p++) {
      const int m = a_mr + p * 32;
      const float4 v = xv[p];
      const uint32_t h0 = pack_bf16x2(v.x, v.y);
      const uint32_t h1 = pack_bf16x2(v.z, v.w);
      const float2 f0 = unpack_bf16x2(h0);
      const float2 f1 = unpack_bf16x2(h1);
      const uint32_t l0 = pack_bf16x2(v.x - f0.x, v.y - f0.y);
      const uint32_t l1 = pack_bf16x2(v.z - f1.x, v.w - f1.y);
      const uint32_t o = sw128((uint32_t)(m * 128 + a_c4 * 8));
      *(uint2*)(st + o)          = make_uint2(h0, h1);
      *(uint2*)(st + kTileB + o) = make_uint2(l0, l1);
      // rowsum over this group's 64 cols (16-lane half-warp reduction)
      float rs = (v.x + v.y) + (v.z + v.w);
      rs += __shfl_xor_sync(0xffffffffu, rs, 1);
      rs += __shfl_xor_sync(0xffffffffu, rs, 2);
      rs += __shfl_xor_sync(0xffffffffu, rs, 4);
      rs += __shfl_xor_sync(0xffffffffu, rs, 8);
      if ((l & 15) == 0) {
        const __nv_bfloat16 rh = __float2bfloat16(rs);
        const __nv_bfloat16 rl = __float2bfloat16(rs - __bfloat162float(rh));
        *(__nv_bfloat16*)(smem + kRZoff          + m * 64 + ch * 2) = rh;
        *(__nv_bfloat16*)(smem + kRZoff + 8192   + m * 64 + ch * 2) = rl;
      }
    }
    // B tile: q -> bf16 (exact), N-major rows (128B), SW128
#pragma unroll
    for (int p = 0; p < 4; p++) {
      const int kp = b_kpb + 4 * p;
      const uint32_t h_r0 = pack_bf16x2((float)qva[p].x, (float)qvb[p].x);
      const uint32_t h_r1 = pack_bf16x2((float)qva[p].y, (float)qvb[p].y);
      *(uint32_t*)(st + 2 * kTileB + sw128((uint32_t)(b_n0 * 128 + kp * 4)))       = h_r0;
      *(uint32_t*)(st + 2 * kTileB + sw128((uint32_t)((b_n0 + 1) * 128 + kp * 4))) = h_r1;
    }
    // s array + Z (zp) hi/lo columns for this group
    if (tid < 128) {
      const float s   = szv.x;
      const float zpf = szv.y - 8.f * s;
      *(float*)(st + 3 * kTileB + tid * 4) = s;
      const __nv_bfloat16 zh = __float2bfloat16(zpf);
      const __nv_bfloat16 zl = __float2bfloat16(zpf - __bfloat162float(zh));
      *(__nv_bfloat16*)(smem + kRZoff + 16384 + tid * 64 + ch * 2) = zh;
      *(__nv_bfloat16*)(smem + kRZoff + 24576 + tid * 64 + ch * 2) = zl;
    }
  };

  // ---- main pipeline: single barrier per chunk, double-buffered ----
  load_chunk(0);
  for (int ch = 0; ch < kNCh; ch++) {
    const int buf = ch & 1;
    store_chunk(buf, ch);
    __syncthreads();
    if (ch + 1 < kNCh) load_chunk(ch + 1);

    float P[32];
#pragma unroll
    for (int i = 0; i < 32; i++) P[i] = 0.f;

    const uint32_t base = sbase + buf * kStageB;
#pragma unroll
    for (int ks = 0; ks < 4; ks++) {
      uint32_t Ah[2][4], Al[2][4], Bq[4][2];
#pragma unroll
      for (int mi = 0; mi < 2; mi++) {
        const int row = rowA0 + mi * 16;
        const uint32_t o = (uint32_t)(row * 128) +
                           (((uint32_t)(ks * 32 + segA * 16)) ^ ((row & 7) << 4));
        ldsm_x4(Ah[mi], base + o);
        ldsm_x4(Al[mi], base + kTileB + o);
      }
#pragma unroll
      for (int ni = 0; ni < 4; ni++) {
        const int row = rowB0 + ni * 8;
        const uint32_t o = (uint32_t)(row * 128) +
                           (((uint32_t)(ks * 32 + segB * 16)) ^ ((row & 7) << 4));
        ldsm_x2(Bq[ni], base + 2 * kTileB + o);
      }
#pragma unroll
      for (int mi = 0; mi < 2; mi++)
#pragma unroll
        for (int ni = 0; ni < 4; ni++) {
          float* c = &P[(mi * 4 + ni) * 4];
          mma_bf16(c, Ah[mi], Bq[ni]);
          mma_bf16(c, Al[mi], Bq[ni]);
        }
    }

    // rescale: master += P * s[n]
    const uint32_t sb = base + 3 * kTileB;
#pragma unroll
    for (int ni = 0; ni < 4; ni++) {
      float2 sv;
      asm volatile("ld.shared.v2.f32 {%0,%1}, [%2];"
                   : "=f"(sv.x), "=f"(sv.y)
                   : "r"(sb + (uint32_t)((wn * 32 + ni * 8 + (l & 3) * 2) * 4)));
#pragma unroll
      for (int mi = 0; mi < 2; mi++) {
        float* f = &mast[(mi * 4 + ni) * 4];
        const float* p = &P[(mi * 4 + ni) * 4];
        f[0] += p[0] * sv.x;
        f[1] += p[1] * sv.y;
        f[2] += p[2] * sv.x;
        f[3] += p[3] * sv.y;
      }
    }
    // no second barrier: store(buf) at ch+2 is ordered by the barrier at ch+1
  }

  // ---- rank-32 zero-point correction: master += R @ Z^T (3-term hi/lo) ----
  {
    const uint32_t Rh = sbase + kRZoff;
    const uint32_t Rl = Rh + 8192;
    const uint32_t Zh = Rh + 16384;
    const uint32_t Zl = Rh + 24576;
#pragma unroll
    for (int ks = 0; ks < 2; ks++) {
      uint32_t Arh[2][4], Arl[2][4], Bzh[4][2], Bzl[4][2];
#pragma unroll
      for (int mi = 0; mi < 2; mi++) {
        const uint32_t o = (uint32_t)((rowA0 + mi * 16) * 64 + ks * 32 + segA * 16);
        ldsm_x4(Arh[mi], Rh + o);
        ldsm_x4(Arl[mi], Rl + o);
      }
#pragma unroll
      for (int ni = 0; ni < 4; ni++) {
        const uint32_t o = (uint32_t)((rowB0 + ni * 8) * 64 + ks * 32 + segB * 16);
        ldsm_x2(Bzh[ni], Zh + o);
        ldsm_x2(Bzl[ni], Zl + o);
      }
#pragma unroll
      for (int mi = 0; mi < 2; mi++)
#pragma unroll
        for (int ni = 0; ni < 4; ni++) {
          float* c = &mast[(mi * 4 + ni) * 4];
          mma_bf16(c, Arh[mi], Bzh[ni]);
          mma_bf16(c, Arl[mi], Bzh[ni]);
          mma_bf16(c, Arh[mi], Bzl[ni]);
        }
    }
  }

  // ---- epilogue ----
#pragma unroll
  for (int mi = 0; mi < 2; mi++) {
#pragma unroll
    for (int ni = 0; ni < 4; ni++) {
      const float* c = &mast[(mi * 4 + ni) * 4];
      const int r0  = wm * 32 + mi * 16 + (l >> 2);
      const int col = n0 + wn * 32 + ni * 8 + (l & 3) * 2;
      if (r0 < nrows)
        *(float2*)(out + (size_t)(row0 + r0) * kOUT + col) = make_float2(c[0], c[1]);
      if (r0 + 8 < nrows)
        *(float2*)(out + (size_t)(row0 + r0 + 8) * kOUT + col) = make_float2(c[2], c[3]);
    }
  }
}

}  // namespace

// ---------------------------------------------------------------------------

extern "C" void kernel_launch(void* const* d_in, const int* in_sizes, int n_in,
                              void* d_out, int out_size) {
  (void)in_sizes; (void)n_in; (void)out_size;
  const float* x   = (const float*)d_in[0];
  const int*   qw  = (const int*)d_in[1];
  const float* snz = (const float*)d_in[2];
  const int*   tpe = (const int*)d_in[3];
  float* out = (float*)d_out;

  (void)cudaFuncSetAttribute(hqq_mma_kernel,
                             cudaFuncAttributeMaxDynamicSharedMemorySize, kSmemB);

  dim3 grid(kOUT / kBN, 2048 / kBM, kE);   // (16, 16, 8); empty m-tiles early-exit
  hqq_mma_kernel<<<grid, kThreads, kSmemB>>>(x, qw, snz, tpe, out);
}